// round 9
// baseline (speedup 1.0000x reference)
#include <cuda_runtime.h>
#include <math.h>

// VolatilityLoss: mean((std3(pred) - std3(targ))^2), window w=3.
// B=512, S=8192, L=8190 outputs/row.
// SINGLE-WAVE layout: 512 blocks (one per row) x 256 threads, 32 elems/thread,
// launch_bounds(256,4) -> <=64 regs -> 4 blocks/SM -> capacity 592 >= 512.
// Packed f32x2 rolling chain: 6*var_i = e_i^2+e_{i+1}^2+(e_i+e_{i+1})^2,
// (sqrt(vp)-sqrt(vt))^2 = (vp6+vt6-2*sqrt(vp6*vt6))/6 (deferred /6).

#define B_ROWS 512
#define S_LEN  8192
#define L_OUT  (S_LEN - 2)
#define NBLOCKS 512
#define NTHREADS 256   // thread t covers row elems [32t, 32t+32)

typedef unsigned long long u64;

__device__ float        g_partials[NBLOCKS];
__device__ unsigned int g_counter = 0;   // monotone across graph replays

__device__ __forceinline__ float sqrt_approx(float x) {
    float r;
    asm("sqrt.approx.f32 %0, %1;" : "=f"(r) : "f"(x));
    return r;
}

#define PACK2(dst, lo, hi) \
    asm("mov.b64 %0, {%1, %2};" : "=l"(dst) : "f"(lo), "f"(hi))
#define UNPACK2(lo, hi, src) \
    asm("mov.b64 {%0, %1}, %2;" : "=f"(lo), "=f"(hi) : "l"(src))
#define FMA2(dst, a, b, c) \
    asm("fma.rn.f32x2 %0, %1, %2, %3;" : "=l"(dst) : "l"(a), "l"(b), "l"(c))
#define ADD2(dst, a, b) \
    asm("add.rn.f32x2 %0, %1, %2;" : "=l"(dst) : "l"(a), "l"(b))
#define MUL2(dst, a, b) \
    asm("mul.rn.f32x2 %0, %1, %2;" : "=l"(dst) : "l"(a), "l"(b))

// One chain step: consume element (pel, tel) = x_{j+2}; window j valid if `v`.
#define STEP(pel, tel, v)                                   \
    do {                                                    \
        u64 Pn, E, Gc, F, GS, V;                            \
        PACK2(Pn, pel, tel);                                \
        FMA2(E, Pn, M1, Pc);      /* E = Pc - Pn */         \
        MUL2(Gc, E, E);                                     \
        ADD2(F, Ep, E);                                     \
        ADD2(GS, Gp, Gc);                                   \
        FMA2(V, F, F, GS);        /* {6vp, 6vt} >= 0 */     \
        if (v) {                                            \
            ADD2(accV, accV, V);                            \
            float _vp, _vt;                                 \
            UNPACK2(_vp, _vt, V);                           \
            accR += sqrt_approx(_vp * _vt);                 \
        }                                                   \
        Ep = E; Gp = Gc; Pc = Pn;                           \
    } while (0)

__global__ void __launch_bounds__(NTHREADS, 4)
vol_loss_fused(const float* __restrict__ pred, const float* __restrict__ targ,
               float* __restrict__ out) {
    const int t    = threadIdx.x;
    const int lane = t & 31;
    const float* pb = pred + ((size_t)blockIdx.x << 13) + (t << 5);
    const float* tb = targ + ((size_t)blockIdx.x << 13) + (t << 5);

    // 16 LDG.128 covering the thread's 32 elements of each array.
    float4 a0 = ((const float4*)pb)[0], a1 = ((const float4*)pb)[1];
    float4 a2 = ((const float4*)pb)[2], a3 = ((const float4*)pb)[3];
    float4 a4 = ((const float4*)pb)[4], a5 = ((const float4*)pb)[5];
    float4 a6 = ((const float4*)pb)[6], a7 = ((const float4*)pb)[7];
    float4 b0 = ((const float4*)tb)[0], b1 = ((const float4*)tb)[1];
    float4 b2 = ((const float4*)tb)[2], b3 = ((const float4*)tb)[3];
    float4 b4 = ((const float4*)tb)[4], b5 = ((const float4*)tb)[5];
    float4 b6 = ((const float4*)tb)[6], b7 = ((const float4*)tb)[7];

    // Elements 32,33 = next thread's elements 0,1 (shuffle); lane 31 loads
    // them; thread 255 is the row end (windows 30,31 invalid).
    bool full = (t != NTHREADS - 1);
    float p32 = __shfl_down_sync(0xffffffffu, a0.x, 1);
    float p33 = __shfl_down_sync(0xffffffffu, a0.y, 1);
    float t32 = __shfl_down_sync(0xffffffffu, b0.x, 1);
    float t33 = __shfl_down_sync(0xffffffffu, b0.y, 1);
    if (lane == 31) {
        p32 = p33 = t32 = t33 = 0.0f;
        if (full) {
            float2 pe2 = ((const float2*)(pb + 32))[0];
            float2 te2 = ((const float2*)(tb + 32))[0];
            p32 = pe2.x; p33 = pe2.y; t32 = te2.x; t33 = te2.y;
        }
    }

    u64 M1, accV;
    PACK2(M1,   -1.0f, -1.0f);
    PACK2(accV,  0.0f,  0.0f);
    float accR = 0.0f;

    // Prologue: P0, P1, e0 = x0 - x1.
    u64 P0, Pc, Ep, Gp;
    PACK2(P0, a0.x, b0.x);
    PACK2(Pc, a0.y, b0.y);
    FMA2(Ep, Pc, M1, P0);
    MUL2(Gp, Ep, Ep);

    STEP(a0.z, b0.z, true);  STEP(a0.w, b0.w, true);   // j=0,1
    STEP(a1.x, b1.x, true);  STEP(a1.y, b1.y, true);
    STEP(a1.z, b1.z, true);  STEP(a1.w, b1.w, true);
    STEP(a2.x, b2.x, true);  STEP(a2.y, b2.y, true);
    STEP(a2.z, b2.z, true);  STEP(a2.w, b2.w, true);
    STEP(a3.x, b3.x, true);  STEP(a3.y, b3.y, true);
    STEP(a3.z, b3.z, true);  STEP(a3.w, b3.w, true);
    STEP(a4.x, b4.x, true);  STEP(a4.y, b4.y, true);
    STEP(a4.z, b4.z, true);  STEP(a4.w, b4.w, true);
    STEP(a5.x, b5.x, true);  STEP(a5.y, b5.y, true);
    STEP(a5.z, b5.z, true);  STEP(a5.w, b5.w, true);
    STEP(a6.x, b6.x, true);  STEP(a6.y, b6.y, true);
    STEP(a6.z, b6.z, true);  STEP(a6.w, b6.w, true);
    STEP(a7.x, b7.x, true);  STEP(a7.y, b7.y, true);
    STEP(a7.z, b7.z, true);  STEP(a7.w, b7.w, true);   // j=28,29
    STEP(p32,  t32,  full);  STEP(p33,  t33,  full);   // j=30,31

    float vps, vts;
    UNPACK2(vps, vts, accV);
    float acc = (vps + vts) - 2.0f * accR;   // still scaled by 6

    // Deterministic intra-block reduction.
    #pragma unroll
    for (int o = 16; o > 0; o >>= 1)
        acc += __shfl_down_sync(0xffffffffu, acc, o);

    __shared__ float red[NTHREADS / 32];
    int warp = t >> 5;
    if (lane == 0) red[warp] = acc;
    __syncthreads();

    __shared__ bool is_last;
    if (t == 0) {
        float v = 0.0f;
        #pragma unroll
        for (int w = 0; w < NTHREADS / 32; ++w) v += red[w];
        g_partials[blockIdx.x] = v;
        __threadfence();
        unsigned int old = atomicAdd(&g_counter, 1u);
        is_last = ((old + 1u) % (unsigned)NBLOCKS) == 0u;
    }
    __syncthreads();

    if (!is_last) return;

    // Last block: deterministic final reduction; fold the deferred /6.
    __shared__ double sh[NTHREADS];
    double s = 0.0;
    for (int i = t; i < NBLOCKS; i += NTHREADS)
        s += (double)g_partials[i];
    sh[t] = s;
    __syncthreads();
    #pragma unroll
    for (int stride = NTHREADS / 2; stride > 0; stride >>= 1) {
        if (t < stride) sh[t] += sh[t + stride];
        __syncthreads();
    }
    if (t == 0)
        out[0] = (float)(sh[0] / (6.0 * (double)B_ROWS * (double)L_OUT));
}

extern "C" void kernel_launch(void* const* d_in, const int* in_sizes, int n_in,
                              void* d_out, int out_size) {
    const float* pred = (const float*)d_in[0];
    const float* targ = (const float*)d_in[1];
    vol_loss_fused<<<NBLOCKS, NTHREADS>>>(pred, targ, (float*)d_out);
}